// round 5
// baseline (speedup 1.0000x reference)
#include <cuda_runtime.h>
#include <math.h>

#define BB 16
#define NNP 2048
#define IND 64
#define HD 128
#define NOBJ 8
#define NSLOT 24
#define NITER 3

// ---------------- device scratch (static, no allocation) ----------------
__device__ float g_hyp[BB*NNP*HD];
__device__ float g_feats[BB*NNP*HD];
__device__ float g_x2[BB*NNP];
__device__ float g_f2[BB*NNP];
__device__ float g_fr[BB*NNP];
__device__ float g_density[BB*NNP];
__device__ float g_slots[BB*NSLOT*HD];
__device__ float g_s2[BB*NSLOT];
__device__ float g_sr[BB*NSLOT];
__device__ float g_gh[NOBJ*3*HD];
__device__ float g_upd[BB*NSLOT*HD];
__device__ float g_rowsum[BB*NSLOT];

__device__ __forceinline__ float geluf(float x){
    return 0.5f*x*(1.f+erff(x*0.70710678118654752f));
}
__device__ __forceinline__ float sigmoidf(float x){
    return 1.f/(1.f+expf(-x));
}

// ---- packed f32x2 helpers (Blackwell sm_100+) ----
__device__ __forceinline__ unsigned long long pack2(float lo, float hi){
    unsigned long long r;
    asm("mov.b64 %0, {%1,%2};" : "=l"(r) : "f"(lo), "f"(hi));
    return r;
}
__device__ __forceinline__ void fma2(unsigned long long& d, unsigned long long a, unsigned long long b){
    asm("fma.rn.f32x2 %0, %1, %2, %0;" : "+l"(d) : "l"(a), "l"(b));
}
__device__ __forceinline__ void unpack2(unsigned long long v, float& lo, float& hi){
    asm("mov.b64 {%0,%1}, %2;" : "=f"(lo), "=f"(hi) : "l"(v));
}

// ======================= encoder: x -> hyp (tanh(enc@hp_w+hp_b)) =======================
// 128 threads, 32 tokens/block. One 64KB weight buffer reused across 3 stages.
// f32x2 along the OUTPUT dim: weight pairs come free via ulonglong2 smem loads.
__global__ void enc_kernel(const float* __restrict__ x,
    const float* __restrict__ fe_w1, const float* __restrict__ fe_b1,
    const float* __restrict__ ln1_g, const float* __restrict__ ln1_b,
    const float* __restrict__ fe_w2, const float* __restrict__ fe_b2,
    const float* __restrict__ ln2_g, const float* __restrict__ ln2_b,
    const float* __restrict__ hp_w,  const float* __restrict__ hp_b)
{
    extern __shared__ float sm[];
    float* s_w = sm;                        // up to 128*128
    float* s_x = s_w + HD*HD;               // 32*64
    float* s_h = s_x + 32*IND;              // 32*128

    const int tid = threadIdx.x;
    const int tokbase = blockIdx.x*32;
    {
        const float4* xs=(const float4*)(x + (size_t)tokbase*IND); float4* xd=(float4*)s_x;
        for (int i=tid;i<32*IND/4;i+=128) xd[i]=xs[i];
        const float4* a=(const float4*)fe_w1; float4* d=(float4*)s_w;
        for (int i=tid;i<IND*HD/4;i+=128) d[i]=a[i];
    }
    __syncthreads();
    if (tid < 32){
        float s=0.f;
        #pragma unroll 8
        for (int k=0;k<IND;k++){ float v=s_x[tid*IND+k]; s+=v*v; }
        g_x2[tokbase+tid]=s;
    }
    const int w = tid>>5, l = tid&31;

    unsigned long long acc2[8][2];
    // ---- stage A: h1 = gelu(LN(x@W1+b1)) ----
    #pragma unroll
    for (int t=0;t<8;t++){acc2[t][0]=0ull; acc2[t][1]=0ull;}
    {
        const ulonglong2* w2p=(const ulonglong2*)s_w;
        for (int k=0;k<IND;k++){
            ulonglong2 wp = w2p[k*32+l];
            #pragma unroll
            for (int t=0;t<8;t++){
                float xv = s_x[(w*8+t)*IND + k];
                unsigned long long X = pack2(xv,xv);
                fma2(acc2[t][0],X,wp.x); fma2(acc2[t][1],X,wp.y);
            }
        }
    }
    {
        float4 bv=((const float4*)fe_b1)[l];
        float4 gv=((const float4*)ln1_g)[l];
        float4 bt=((const float4*)ln1_b)[l];
        #pragma unroll
        for (int t=0;t<8;t++){
            float v0,v1,v2,v3;
            unpack2(acc2[t][0],v0,v1); unpack2(acc2[t][1],v2,v3);
            v0+=bv.x; v1+=bv.y; v2+=bv.z; v3+=bv.w;
            float s=v0+v1+v2+v3, q=v0*v0+v1*v1+v2*v2+v3*v3;
            #pragma unroll
            for (int o=16;o;o>>=1){ s+=__shfl_xor_sync(0xffffffffu,s,o); q+=__shfl_xor_sync(0xffffffffu,q,o); }
            float mu=s*(1.f/HD), var=q*(1.f/HD)-mu*mu;
            float inv=rsqrtf(var+1e-5f);
            v0=geluf((v0-mu)*inv*gv.x+bt.x); v1=geluf((v1-mu)*inv*gv.y+bt.y);
            v2=geluf((v2-mu)*inv*gv.z+bt.z); v3=geluf((v3-mu)*inv*gv.w+bt.w);
            float4* hv=(float4*)&s_h[(w*8+t)*HD + l*4];
            *hv = make_float4(v0,v1,v2,v3);
        }
    }
    __syncthreads();
    {   // load W2
        const float4* b=(const float4*)fe_w2; float4* d2=(float4*)s_w;
        for (int i=tid;i<HD*HD/4;i+=128) d2[i]=b[i];
    }
    __syncthreads();
    // ---- stage B: enc = LN(h1@W2+b2) ----
    #pragma unroll
    for (int t=0;t<8;t++){acc2[t][0]=0ull; acc2[t][1]=0ull;}
    {
        const ulonglong2* w2p=(const ulonglong2*)s_w;
        for (int k=0;k<HD;k++){
            ulonglong2 wp = w2p[k*32+l];
            #pragma unroll
            for (int t=0;t<8;t++){
                float xv = s_h[(w*8+t)*HD + k];
                unsigned long long X = pack2(xv,xv);
                fma2(acc2[t][0],X,wp.x); fma2(acc2[t][1],X,wp.y);
            }
        }
    }
    float encv[8][4];
    {
        float4 bv=((const float4*)fe_b2)[l];
        float4 gv=((const float4*)ln2_g)[l];
        float4 bt=((const float4*)ln2_b)[l];
        #pragma unroll
        for (int t=0;t<8;t++){
            float v0,v1,v2,v3;
            unpack2(acc2[t][0],v0,v1); unpack2(acc2[t][1],v2,v3);
            v0+=bv.x; v1+=bv.y; v2+=bv.z; v3+=bv.w;
            float s=v0+v1+v2+v3, q=v0*v0+v1*v1+v2*v2+v3*v3;
            #pragma unroll
            for (int o=16;o;o>>=1){ s+=__shfl_xor_sync(0xffffffffu,s,o); q+=__shfl_xor_sync(0xffffffffu,q,o); }
            float mu=s*(1.f/HD), var=q*(1.f/HD)-mu*mu;
            float inv=rsqrtf(var+1e-5f);
            encv[t][0]=(v0-mu)*inv*gv.x+bt.x; encv[t][1]=(v1-mu)*inv*gv.y+bt.y;
            encv[t][2]=(v2-mu)*inv*gv.z+bt.z; encv[t][3]=(v3-mu)*inv*gv.w+bt.w;
        }
    }
    __syncthreads();
    {   // load W3
        const float4* c=(const float4*)hp_w; float4* d3=(float4*)s_w;
        for (int i=tid;i<HD*HD/4;i+=128) d3[i]=c[i];
    }
    #pragma unroll
    for (int t=0;t<8;t++){
        float4* hv=(float4*)&s_h[(w*8+t)*HD + l*4];
        *hv = make_float4(encv[t][0],encv[t][1],encv[t][2],encv[t][3]);
    }
    __syncthreads();
    // ---- stage C: hyp = tanh(enc@hp_w + hp_b) ----
    #pragma unroll
    for (int t=0;t<8;t++){acc2[t][0]=0ull; acc2[t][1]=0ull;}
    {
        const ulonglong2* w2p=(const ulonglong2*)s_w;
        for (int k=0;k<HD;k++){
            ulonglong2 wp = w2p[k*32+l];
            #pragma unroll
            for (int t=0;t<8;t++){
                float xv = s_h[(w*8+t)*HD + k];
                unsigned long long X = pack2(xv,xv);
                fma2(acc2[t][0],X,wp.x); fma2(acc2[t][1],X,wp.y);
            }
        }
    }
    {
        float4 bv=((const float4*)hp_b)[l];
        #pragma unroll
        for (int t=0;t<8;t++){
            float v0,v1,v2,v3;
            unpack2(acc2[t][0],v0,v1); unpack2(acc2[t][1],v2,v3);
            float4 hv;
            hv.x=tanhf(v0+bv.x); hv.y=tanhf(v1+bv.y);
            hv.z=tanhf(v2+bv.z); hv.w=tanhf(v3+bv.w);
            ((float4*)(g_hyp + (size_t)(tokbase + w*8 + t)*HD))[l]=hv;
        }
    }
}

// ======================= density: register-tiled gram + per-thread top-6 =======================
__device__ __forceinline__ void ins6(float t[6], float v){
    if (v < t[5]){
        t[5]=v;
        #pragma unroll
        for (int s=5;s>0;s--){ if (t[s]<t[s-1]){ float tmp=t[s-1]; t[s-1]=t[s]; t[s]=tmp; } }
    }
}

#define DENS_SMEM_FLOATS (4096 + 8192 + 128)   // 12416 floats = 49664 B

__global__ void __launch_bounds__(256) dens_kernel(const float* __restrict__ x,
                                                   float* __restrict__ dens_out)
{
    extern __shared__ float sm[];
    float* s_xi  = sm;                     // [k][64 i]   4096
    float* s_xj  = sm + 4096;              // [k][128 j]  8192
    float* s_x2j = sm + 4096 + 8192;       // [128]
    float* s_cand= sm;                     // reuse: [64][97]

    const int b  = blockIdx.y;
    const int i0 = blockIdx.x * 64;
    const int tid = threadIdx.x;
    const int rg = tid >> 4;
    const int cg = tid & 15;

    {
        const float* xb = x + ((size_t)b*NNP + i0)*IND;
        #pragma unroll
        for (int p=0;p<4;p++){
            int idx = tid + 256*p;
            int i = idx & 63, k4 = idx >> 6;
            float4 v = ((const float4*)(xb + (size_t)i*IND))[k4];
            s_xi[(4*k4+0)*64 + i] = v.x;
            s_xi[(4*k4+1)*64 + i] = v.y;
            s_xi[(4*k4+2)*64 + i] = v.z;
            s_xi[(4*k4+3)*64 + i] = v.w;
        }
    }

    float t6[4][6];
    #pragma unroll
    for (int r=0;r<4;r++){
        #pragma unroll
        for (int s=0;s<6;s++) t6[r][s]=1e30f;
    }

    for (int jt=0;jt<16;jt++){
        __syncthreads();
        {
            const float* xb = x + ((size_t)b*NNP + jt*128)*IND;
            #pragma unroll
            for (int p=0;p<8;p++){
                int idx = tid + 256*p;
                int j = idx & 127, k4 = idx >> 7;
                float4 v = ((const float4*)(xb + (size_t)j*IND))[k4];
                s_xj[(4*k4+0)*128 + j] = v.x;
                s_xj[(4*k4+1)*128 + j] = v.y;
                s_xj[(4*k4+2)*128 + j] = v.z;
                s_xj[(4*k4+3)*128 + j] = v.w;
            }
            if (tid < 128) s_x2j[tid] = g_x2[b*NNP + jt*128 + tid];
        }
        __syncthreads();

        unsigned long long acc2[4][4];
        #pragma unroll
        for (int r=0;r<4;r++){
            #pragma unroll
            for (int c=0;c<4;c++) acc2[r][c]=0ull;
        }
        #pragma unroll 4
        for (int k=0;k<64;k++){
            float4 av = *(const float4*)&s_xi[k*64 + rg*4];
            // B pairs come free: ulonglong2 loads = LDS.128 into register pairs
            ulonglong2 bp0 = *(const ulonglong2*)&s_xj[k*128 + cg*8];
            ulonglong2 bp1 = *(const ulonglong2*)&s_xj[k*128 + cg*8 + 4];
            unsigned long long A0=pack2(av.x,av.x), A1=pack2(av.y,av.y);
            unsigned long long A2=pack2(av.z,av.z), A3=pack2(av.w,av.w);
            fma2(acc2[0][0],A0,bp0.x); fma2(acc2[0][1],A0,bp0.y); fma2(acc2[0][2],A0,bp1.x); fma2(acc2[0][3],A0,bp1.y);
            fma2(acc2[1][0],A1,bp0.x); fma2(acc2[1][1],A1,bp0.y); fma2(acc2[1][2],A1,bp1.x); fma2(acc2[1][3],A1,bp1.y);
            fma2(acc2[2][0],A2,bp0.x); fma2(acc2[2][1],A2,bp0.y); fma2(acc2[2][2],A2,bp1.x); fma2(acc2[2][3],A2,bp1.y);
            fma2(acc2[3][0],A3,bp0.x); fma2(acc2[3][1],A3,bp0.y); fma2(acc2[3][2],A3,bp1.x); fma2(acc2[3][3],A3,bp1.y);
        }
        float4 xa = *(const float4*)&s_x2j[cg*8];
        float4 xb4= *(const float4*)&s_x2j[cg*8+4];
        #pragma unroll
        for (int r=0;r<4;r++){
            float d0,d1;
            unpack2(acc2[r][0],d0,d1); ins6(t6[r], xa.x - 2.f*d0); ins6(t6[r], xa.y - 2.f*d1);
            unpack2(acc2[r][1],d0,d1); ins6(t6[r], xa.z - 2.f*d0); ins6(t6[r], xa.w - 2.f*d1);
            unpack2(acc2[r][2],d0,d1); ins6(t6[r], xb4.x - 2.f*d0); ins6(t6[r], xb4.y - 2.f*d1);
            unpack2(acc2[r][3],d0,d1); ins6(t6[r], xb4.z - 2.f*d0); ins6(t6[r], xb4.w - 2.f*d1);
        }
    }
    __syncthreads();
    #pragma unroll
    for (int r=0;r<4;r++){
        float* c = &s_cand[(rg*4+r)*97 + cg*6];
        #pragma unroll
        for (int s=0;s<6;s++) c[s]=t6[r][s];
    }
    __syncthreads();
    if (tid < 64){
        float u[6]={1e30f,1e30f,1e30f,1e30f,1e30f,1e30f};
        const float* row = &s_cand[tid*97];
        for (int m=0;m<96;m++) ins6(u, row[m]);
        float x2i = g_x2[b*NNP + i0 + tid];
        float md = (sqrtf(fmaxf(x2i+u[1],0.f)) + sqrtf(fmaxf(x2i+u[2],0.f))
                  + sqrtf(fmaxf(x2i+u[3],0.f)) + sqrtf(fmaxf(x2i+u[4],0.f))
                  + sqrtf(fmaxf(x2i+u[5],0.f))) * 0.2f;
        float dv = tanhf(md);
        g_density[b*NNP + i0 + tid] = dv;
        dens_out [b*NNP + i0 + tid] = dv;
    }
}

// ======================= feats: Poincare projection =======================
__global__ void feats_kernel()
{
    const int w = threadIdx.x>>5, l = threadIdx.x&31;
    const int n = blockIdx.x*8 + w;
    float4 v = ((const float4*)(g_hyp + (size_t)n*HD))[l];
    float q = v.x*v.x+v.y*v.y+v.z*v.z+v.w*v.w;
    #pragma unroll
    for (int o=16;o;o>>=1) q += __shfl_xor_sync(0xffffffffu,q,o);
    float fn = fmaxf(sqrtf(q),1e-6f);
    float dens = g_density[n];
    float tr = (0.3f+0.5f*(1.f-dens))*0.95f;
    float sc = tr/fn;
    float4 f = make_float4(v.x*sc,v.y*sc,v.z*sc,v.w*sc);
    ((float4*)(g_feats + (size_t)n*HD))[l]=f;
    if (l==0){
        float f2=q*sc*sc;
        g_f2[n]=f2; g_fr[n]=sqrtf(f2);
    }
}

// ======================= slots init (cheap) =======================
__global__ void slots_init_kernel(const float* __restrict__ obj_dirs)
{
    const int w=threadIdx.x>>5, l=threadIdx.x&31;
    if (w<NOBJ){
        float4 v=((const float4*)(obj_dirs + w*HD))[l];
        float q=v.x*v.x+v.y*v.y+v.z*v.z+v.w*v.w;
        #pragma unroll
        for (int o=16;o;o>>=1) q += __shfl_xor_sync(0xffffffffu,q,o);
        float nrm=sqrtf(q);
        float inv=1.f/fmaxf(nrm,1e-12f);
        float4 dn=make_float4(v.x*inv,v.y*inv,v.z*inv,v.w*inv);
        float qn=q*inv*inv;
        const float radii[3]={0.2f,0.5f,0.8f};
        for (int b=0;b<BB;b++){
            #pragma unroll
            for (int lv=0;lv<3;lv++){
                float r=radii[lv];
                ((float4*)(g_slots + (size_t)(b*NSLOT + w*3+lv)*HD))[l] =
                    make_float4(dn.x*r,dn.y*r,dn.z*r,dn.w*r);
                if (l==0){
                    float s2=qn*r*r;
                    g_s2[b*NSLOT + w*3+lv]=s2;
                    g_sr[b*NSLOT + w*3+lv]=sqrtf(s2);
                }
            }
        }
    }
}

// ======================= gh precompute: parallel warp dots =======================
__global__ void gh_kernel(const float* __restrict__ obj_dirs,
                          const float* __restrict__ gru_wh,
                          const float* __restrict__ gru_bh)
{
    const int o = blockIdx.x;
    const int w = threadIdx.x>>5, l = threadIdx.x&31;
    float4 od = ((const float4*)(obj_dirs + (size_t)o*HD))[l];
    for (int m=0;m<48;m++){
        int r = w*48 + m;
        float4 wv = ((const float4*)(gru_wh + (size_t)r*HD))[l];
        float p = od.x*wv.x + od.y*wv.y + od.z*wv.z + od.w*wv.w;
        #pragma unroll
        for (int of=16;of;of>>=1) p += __shfl_xor_sync(0xffffffffu,p,of);
        if (l==0) g_gh[o*3*HD + r] = p + gru_bh[r];
    }
}

// ======================= zero scratch (once, before iteration loop) =======================
__global__ void zero_kernel()
{
    int i = blockIdx.x*256 + threadIdx.x;
    if (i < BB*NSLOT*HD) g_upd[i]=0.f;
    if (i < BB*NSLOT)    g_rowsum[i]=0.f;
}

// ======================= attention iteration (fused attn + sum attn*feats) =======================
__global__ void __launch_bounds__(256) attn_kernel(const float* __restrict__ rs_ptr,
                                                   float* __restrict__ attn_out)
{
    __shared__ float s_slots[NSLOT*HD];
    __shared__ float s_s2[NSLOT], s_sr[NSLOT];
    const int b = blockIdx.x >> 4;
    const int nbase = (blockIdx.x & 15) * 128;
    const int tid=threadIdx.x, w=tid>>5, l=tid&31;
    {
        const float4* ss=(const float4*)(g_slots + (size_t)b*NSLOT*HD);
        float4* sd=(float4*)s_slots;
        for (int i=tid;i<NSLOT*HD/4;i+=256) sd[i]=ss[i];
        if (tid<NSLOT){ s_s2[tid]=g_s2[b*NSLOT+tid]; s_sr[tid]=g_sr[b*NSLOT+tid]; }
    }
    __syncthreads();
    const float rs = *rs_ptr;
    float4 acc[NSLOT];
    #pragma unroll
    for (int k=0;k<NSLOT;k++) acc[k]=make_float4(0.f,0.f,0.f,0.f);
    float rsum=0.f;
    const int lvl = (l<NSLOT)? (l - (l/3)*3) : 0;
    const float basel = (lvl==0)?2.f:((lvl==1)?1.f:0.5f);
    const float s2k = (l<NSLOT)? s_s2[l] : 0.f;
    const float srk = (l<NSLOT)? s_sr[l] : 0.f;
    const float4* slots4=(const float4*)s_slots;

    for (int ii=0;ii<16;ii++){
        const int n = nbase + w*16 + ii;
        const size_t off = (size_t)b*NNP + n;
        float4 f = ((const float4*)(g_feats + off*HD))[l];
        float f2n = g_f2[off];
        float frn = g_fr[off];
        float dens= g_density[off];
        float mod = rs*(dens-0.5f);
        float mydot=0.f;
        #pragma unroll
        for (int k=0;k<NSLOT;k++){
            float4 sv=slots4[k*32+l];
            float p = f.x*sv.x+f.y*sv.y+f.z*sv.z+f.w*sv.w;
            p += __shfl_xor_sync(0xffffffffu,p,16);
            p += __shfl_xor_sync(0xffffffffu,p,8);
            p += __shfl_xor_sync(0xffffffffu,p,4);
            p += __shfl_xor_sync(0xffffffffu,p,2);
            p += __shfl_xor_sync(0xffffffffu,p,1);
            if (l==k) mydot=p;
        }
        float logit=-1e30f;
        if (l<NSLOT){
            float diff2 = fmaxf(f2n + s2k - 2.f*mydot, 0.f);
            float xn = fminf(f2n, 1.f-1e-5f);
            float yn = fminf(s2k, 1.f-1e-5f);
            float den = fmaxf((1.f-xn)*(1.f-yn), 1e-6f);
            float arg = fmaxf(1.f + 2.f*diff2/den, 1.f+1e-6f);
            float hd = acoshf(arg);
            float rd = fabsf(frn-srk);
            float scv = fminf(fmaxf(basel+mod,0.3f),3.f);
            logit = (-hd - 3.f*rd)*scv*10.f;   // /TAU
        }
        float m=logit;
        #pragma unroll
        for (int o=16;o;o>>=1) m=fmaxf(m,__shfl_xor_sync(0xffffffffu,m,o));
        float e=(l<NSLOT)? expf(logit-m):0.f;
        float s=e;
        #pragma unroll
        for (int o=16;o;o>>=1) s+=__shfl_xor_sync(0xffffffffu,s,o);
        float a=e/s;
        if (l<NSLOT){
            attn_out[((size_t)b*NSLOT+l)*NNP + n]=a;
            rsum += a;
        }
        #pragma unroll
        for (int k=0;k<NSLOT;k++){
            float ak=__shfl_sync(0xffffffffu,a,k);
            acc[k].x=fmaf(ak,f.x,acc[k].x); acc[k].y=fmaf(ak,f.y,acc[k].y);
            acc[k].z=fmaf(ak,f.z,acc[k].z); acc[k].w=fmaf(ak,f.w,acc[k].w);
        }
    }
    if (l<NSLOT) atomicAdd(&g_rowsum[b*NSLOT+l], rsum);
    #pragma unroll
    for (int k=0;k<NSLOT;k++){
        float* up = g_upd + ((size_t)b*NSLOT+k)*HD + l*4;
        atomicAdd(up+0,acc[k].x); atomicAdd(up+1,acc[k].y);
        atomicAdd(up+2,acc[k].z); atomicAdd(up+3,acc[k].w);
    }
}

// ======================= GRU + MLP + renorm -> new slots (+ zero consumed scratch) =======================
__device__ __forceinline__ float blksum128(float v, volatile float* red){
    #pragma unroll
    for (int o=16;o;o>>=1) v += __shfl_xor_sync(0xffffffffu,v,o);
    __syncthreads();
    if ((threadIdx.x&31)==0) red[threadIdx.x>>5]=v;
    __syncthreads();
    return red[0]+red[1]+red[2]+red[3];
}

__global__ void gru_kernel(const float* __restrict__ obj_dirs,
    const float* __restrict__ gru_wi, const float* __restrict__ gru_bi,
    const float* __restrict__ mlp_w1, const float* __restrict__ mlp_b1,
    const float* __restrict__ mlp_w2, const float* __restrict__ mlp_b2,
    const float* __restrict__ norm_g, const float* __restrict__ norm_b,
    float* __restrict__ slots_out)
{
    __shared__ float s_buf[HD];
    __shared__ float s_red[4];
    const int b = blockIdx.x >> 3, o = blockIdx.x & 7;
    const int h = threadIdx.x;
    float ou=0.f;
    #pragma unroll
    for (int lv=0;lv<3;lv++){
        int k=o*3+lv;
        ou += g_upd[((size_t)b*NSLOT+k)*HD + h] / (g_rowsum[b*NSLOT+k]+1e-8f);
    }
    s_buf[h]=ou; __syncthreads();
    // zero the scratch this block exclusively owns, for the next attn iteration
    #pragma unroll
    for (int lv=0;lv<3;lv++){
        int k=o*3+lv;
        g_upd[((size_t)b*NSLOT+k)*HD + h]=0.f;
        if (h==lv) g_rowsum[b*NSLOT+k]=0.f;
    }
    float gi[3];
    #pragma unroll
    for (int p=0;p<3;p++){
        int r=p*HD+h;
        float a=gru_bi[r];
        const float* wr=gru_wi+(size_t)r*HD;
        #pragma unroll 8
        for (int hh=0;hh<HD;hh++) a=fmaf(s_buf[hh],wr[hh],a);
        gi[p]=a;
    }
    float hr=g_gh[o*3*HD + h], hz=g_gh[o*3*HD + HD + h], hn=g_gh[o*3*HD + 2*HD + h];
    float rr=sigmoidf(gi[0]+hr);
    float z =sigmoidf(gi[1]+hz);
    float nnv=tanhf(gi[2]+rr*hn);
    float oldh=obj_dirs[o*HD+h];
    float nd=(1.f-z)*nnv + z*oldh;
    float s = blksum128(nd, s_red);
    float q = blksum128(nd*nd, s_red);
    float mu=s*(1.f/HD), var=q*(1.f/HD)-mu*mu;
    float ln=(nd-mu)*rsqrtf(var+1e-5f)*norm_g[h]+norm_b[h];
    __syncthreads(); s_buf[h]=ln; __syncthreads();
    float m1=mlp_b1[h];
    {
        const float* w1=mlp_w1;
        #pragma unroll 8
        for (int hh=0;hh<HD;hh++) m1=fmaf(s_buf[hh],w1[(size_t)hh*HD+h],m1);
    }
    m1=geluf(m1);
    __syncthreads(); s_buf[h]=m1; __syncthreads();
    float m2=mlp_b2[h];
    {
        const float* w2=mlp_w2;
        #pragma unroll 8
        for (int hh=0;hh<HD;hh++) m2=fmaf(s_buf[hh],w2[(size_t)hh*HD+h],m2);
    }
    float nd2 = nd + 0.2f*m2;
    float q2 = blksum128(nd2*nd2, s_red);
    float nrm = fmaxf(sqrtf(q2),1e-12f);
    float ndn = nd2/nrm;
    float qn = q2/(nrm*nrm);
    const float radii[3]={0.2f,0.5f,0.8f};
    #pragma unroll
    for (int lv=0;lv<3;lv++){
        float r=radii[lv];
        float v=ndn*r;
        size_t idx=((size_t)b*NSLOT + o*3+lv)*HD + h;
        g_slots[idx]=v;
        slots_out[idx]=v;
    }
    if (h<3){
        float r=radii[h];
        float s2v=qn*r*r;
        g_s2[b*NSLOT + o*3 + h]=s2v;
        g_sr[b*NSLOT + o*3 + h]=sqrtf(s2v);
    }
}

// ======================= host launch =======================
extern "C" void kernel_launch(void* const* d_in, const int* in_sizes, int n_in,
                              void* d_out, int out_size)
{
    const float* x      = (const float*)d_in[0];
    const float* fe_w1  = (const float*)d_in[1];
    const float* fe_b1  = (const float*)d_in[2];
    const float* ln1_g  = (const float*)d_in[3];
    const float* ln1_b  = (const float*)d_in[4];
    const float* fe_w2  = (const float*)d_in[5];
    const float* fe_b2  = (const float*)d_in[6];
    const float* ln2_g  = (const float*)d_in[7];
    const float* ln2_b  = (const float*)d_in[8];
    const float* hp_w   = (const float*)d_in[9];
    const float* hp_b   = (const float*)d_in[10];
    const float* obj_dirs = (const float*)d_in[11];
    const float* radius_scale = (const float*)d_in[12];
    const float* gru_wi = (const float*)d_in[13];
    const float* gru_wh = (const float*)d_in[14];
    const float* gru_bi = (const float*)d_in[15];
    const float* gru_bh = (const float*)d_in[16];
    const float* mlp_w1 = (const float*)d_in[17];
    const float* mlp_b1 = (const float*)d_in[18];
    const float* mlp_w2 = (const float*)d_in[19];
    const float* mlp_b2 = (const float*)d_in[20];
    const float* norm_g = (const float*)d_in[21];
    const float* norm_b = (const float*)d_in[22];

    float* out = (float*)d_out;
    float* slots_out = out;                                   // [16,24,128]
    float* attn_out  = out + BB*NSLOT*HD;                     // [16,24,2048]
    float* dens_out  = attn_out + (size_t)BB*NSLOT*NNP;       // [16,2048]

    size_t encSmem = (size_t)(HD*HD + 32*IND + 32*HD)*sizeof(float);   // 90KB
    cudaFuncSetAttribute(enc_kernel, cudaFuncAttributeMaxDynamicSharedMemorySize, (int)encSmem);
    size_t densSmem = (size_t)DENS_SMEM_FLOATS*sizeof(float);          // 49,664 B
    cudaFuncSetAttribute(dens_kernel, cudaFuncAttributeMaxDynamicSharedMemorySize, (int)densSmem);

    // Order chosen so the ncu capture (0-based launch #3) profiles dens_kernel.
    enc_kernel<<<BB*NNP/32, 128, encSmem>>>(x, fe_w1, fe_b1, ln1_g, ln1_b,
                                            fe_w2, fe_b2, ln2_g, ln2_b, hp_w, hp_b);   // 0
    slots_init_kernel<<<1, 256>>>(obj_dirs);                                           // 1
    gh_kernel<<<NOBJ, 256>>>(obj_dirs, gru_wh, gru_bh);                                // 2
    {
        dim3 g(NNP/64, BB);
        dens_kernel<<<g, 256, densSmem>>>(x, dens_out);                                // 3  <- profiled
    }
    feats_kernel<<<BB*NNP/8, 256>>>();                                                 // 4
    zero_kernel<<<(BB*NSLOT*HD+255)/256, 256>>>();                                     // 5

    for (int it=0; it<NITER; it++){
        attn_kernel<<<BB*16, 256>>>(radius_scale, attn_out);
        gru_kernel<<<BB*NOBJ, 128>>>(obj_dirs, gru_wi, gru_bi,
                                     mlp_w1, mlp_b1, mlp_w2, mlp_b2,
                                     norm_g, norm_b, slots_out);
    }
}

// round 6
// speedup vs baseline: 1.7876x; 1.7876x over previous
#include <cuda_runtime.h>
#include <cuda_bf16.h>
#include <math.h>

#define BB 16
#define NNP 2048
#define IND 64
#define HD 128
#define NOBJ 8
#define NSLOT 24
#define NITER 3

// ---------------- device scratch (static, no allocation) ----------------
__device__ float g_hyp[BB*NNP*HD];
__device__ float g_feats[BB*NNP*HD];
__device__ float g_x2[BB*NNP];
__device__ float g_f2[BB*NNP];
__device__ float g_fr[BB*NNP];
__device__ float g_density[BB*NNP];
__device__ float g_slots[BB*NSLOT*HD];
__device__ float g_s2[BB*NSLOT];
__device__ float g_sr[BB*NSLOT];
__device__ float g_gh[NOBJ*3*HD];
__device__ float g_upd[BB*NSLOT*HD];
__device__ float g_rowsum[BB*NSLOT];
__device__ __nv_bfloat162 g_xbf2[BB*NNP*IND/2];   // x in bf16 (density path only)

__device__ __forceinline__ float geluf(float x){
    return 0.5f*x*(1.f+erff(x*0.70710678118654752f));
}
__device__ __forceinline__ float sigmoidf(float x){
    return 1.f/(1.f+expf(-x));
}

// ======================= encoder: x -> hyp (R3 scalar version — proven fastest) =======================
__global__ void enc_kernel(const float* __restrict__ x,
    const float* __restrict__ fe_w1, const float* __restrict__ fe_b1,
    const float* __restrict__ ln1_g, const float* __restrict__ ln1_b,
    const float* __restrict__ fe_w2, const float* __restrict__ fe_b2,
    const float* __restrict__ ln2_g, const float* __restrict__ ln2_b,
    const float* __restrict__ hp_w,  const float* __restrict__ hp_b)
{
    extern __shared__ float sm[];
    float* s_w = sm;                        // up to 128*128
    float* s_x = s_w + HD*HD;               // 32*64
    float* s_h = s_x + 32*IND;              // 32*128

    const int tid = threadIdx.x;
    const int tokbase = blockIdx.x*32;
    {
        const float4* xs=(const float4*)(x + (size_t)tokbase*IND); float4* xd=(float4*)s_x;
        for (int i=tid;i<32*IND/4;i+=128) xd[i]=xs[i];
        const float4* a=(const float4*)fe_w1; float4* d=(float4*)s_w;
        for (int i=tid;i<IND*HD/4;i+=128) d[i]=a[i];
    }
    __syncthreads();
    if (tid < 32){
        float s=0.f;
        #pragma unroll 8
        for (int k=0;k<IND;k++){ float v=s_x[tid*IND+k]; s+=v*v; }
        g_x2[tokbase+tid]=s;
    }
    const int w = tid>>5, l = tid&31;

    float acc[8][4];
    // ---- stage A ----
    #pragma unroll
    for (int t=0;t<8;t++){acc[t][0]=acc[t][1]=acc[t][2]=acc[t][3]=0.f;}
    {
        const float4* w4=(const float4*)s_w;
        for (int k=0;k<IND;k++){
            float4 wv = w4[k*32+l];
            #pragma unroll
            for (int t=0;t<8;t++){
                float xv = s_x[(w*8+t)*IND + k];
                acc[t][0]=fmaf(xv,wv.x,acc[t][0]); acc[t][1]=fmaf(xv,wv.y,acc[t][1]);
                acc[t][2]=fmaf(xv,wv.z,acc[t][2]); acc[t][3]=fmaf(xv,wv.w,acc[t][3]);
            }
        }
    }
    {
        float4 bv=((const float4*)fe_b1)[l];
        float4 gv=((const float4*)ln1_g)[l];
        float4 bt=((const float4*)ln1_b)[l];
        #pragma unroll
        for (int t=0;t<8;t++){
            float v0=acc[t][0]+bv.x, v1=acc[t][1]+bv.y, v2=acc[t][2]+bv.z, v3=acc[t][3]+bv.w;
            float s=v0+v1+v2+v3, q=v0*v0+v1*v1+v2*v2+v3*v3;
            #pragma unroll
            for (int o=16;o;o>>=1){ s+=__shfl_xor_sync(0xffffffffu,s,o); q+=__shfl_xor_sync(0xffffffffu,q,o); }
            float mu=s*(1.f/HD), var=q*(1.f/HD)-mu*mu;
            float inv=rsqrtf(var+1e-5f);
            v0=geluf((v0-mu)*inv*gv.x+bt.x); v1=geluf((v1-mu)*inv*gv.y+bt.y);
            v2=geluf((v2-mu)*inv*gv.z+bt.z); v3=geluf((v3-mu)*inv*gv.w+bt.w);
            float4* hv=(float4*)&s_h[(w*8+t)*HD + l*4];
            *hv = make_float4(v0,v1,v2,v3);
        }
    }
    __syncthreads();
    {   // load W2
        const float4* b=(const float4*)fe_w2; float4* d2=(float4*)s_w;
        for (int i=tid;i<HD*HD/4;i+=128) d2[i]=b[i];
    }
    __syncthreads();
    // ---- stage B ----
    #pragma unroll
    for (int t=0;t<8;t++){acc[t][0]=acc[t][1]=acc[t][2]=acc[t][3]=0.f;}
    {
        const float4* w4=(const float4*)s_w;
        for (int k=0;k<HD;k++){
            float4 wv = w4[k*32+l];
            #pragma unroll
            for (int t=0;t<8;t++){
                float xv = s_h[(w*8+t)*HD + k];
                acc[t][0]=fmaf(xv,wv.x,acc[t][0]); acc[t][1]=fmaf(xv,wv.y,acc[t][1]);
                acc[t][2]=fmaf(xv,wv.z,acc[t][2]); acc[t][3]=fmaf(xv,wv.w,acc[t][3]);
            }
        }
    }
    {
        float4 bv=((const float4*)fe_b2)[l];
        float4 gv=((const float4*)ln2_g)[l];
        float4 bt=((const float4*)ln2_b)[l];
        #pragma unroll
        for (int t=0;t<8;t++){
            float v0=acc[t][0]+bv.x, v1=acc[t][1]+bv.y, v2=acc[t][2]+bv.z, v3=acc[t][3]+bv.w;
            float s=v0+v1+v2+v3, q=v0*v0+v1*v1+v2*v2+v3*v3;
            #pragma unroll
            for (int o=16;o;o>>=1){ s+=__shfl_xor_sync(0xffffffffu,s,o); q+=__shfl_xor_sync(0xffffffffu,q,o); }
            float mu=s*(1.f/HD), var=q*(1.f/HD)-mu*mu;
            float inv=rsqrtf(var+1e-5f);
            acc[t][0]=(v0-mu)*inv*gv.x+bt.x; acc[t][1]=(v1-mu)*inv*gv.y+bt.y;
            acc[t][2]=(v2-mu)*inv*gv.z+bt.z; acc[t][3]=(v3-mu)*inv*gv.w+bt.w;
        }
    }
    __syncthreads();
    {   // load W3
        const float4* c=(const float4*)hp_w; float4* d3=(float4*)s_w;
        for (int i=tid;i<HD*HD/4;i+=128) d3[i]=c[i];
    }
    #pragma unroll
    for (int t=0;t<8;t++){
        float4* hv=(float4*)&s_h[(w*8+t)*HD + l*4];
        *hv = make_float4(acc[t][0],acc[t][1],acc[t][2],acc[t][3]);
    }
    __syncthreads();
    // ---- stage C ----
    #pragma unroll
    for (int t=0;t<8;t++){acc[t][0]=acc[t][1]=acc[t][2]=acc[t][3]=0.f;}
    {
        const float4* w4=(const float4*)s_w;
        for (int k=0;k<HD;k++){
            float4 wv = w4[k*32+l];
            #pragma unroll
            for (int t=0;t<8;t++){
                float xv = s_h[(w*8+t)*HD + k];
                acc[t][0]=fmaf(xv,wv.x,acc[t][0]); acc[t][1]=fmaf(xv,wv.y,acc[t][1]);
                acc[t][2]=fmaf(xv,wv.z,acc[t][2]); acc[t][3]=fmaf(xv,wv.w,acc[t][3]);
            }
        }
    }
    {
        float4 bv=((const float4*)hp_b)[l];
        #pragma unroll
        for (int t=0;t<8;t++){
            float4 hv;
            hv.x=tanhf(acc[t][0]+bv.x); hv.y=tanhf(acc[t][1]+bv.y);
            hv.z=tanhf(acc[t][2]+bv.z); hv.w=tanhf(acc[t][3]+bv.w);
            ((float4*)(g_hyp + (size_t)(tokbase + w*8 + t)*HD))[l]=hv;
        }
    }
}

// ======================= x -> bf16 prep =======================
__global__ void xbf_kernel(const float* __restrict__ x)
{
    int i = blockIdx.x*256 + threadIdx.x;           // BB*NNP*IND/2 pairs
    float2 v = ((const float2*)x)[i];
    g_xbf2[i] = __float22bfloat162_rn(v);
}

// ======================= density: bf16 mma.sync gram + top-6 =======================
// Block 256 thr = 8 warps. i-tile 64 rows: warp -> rowgroup (w&3)*16, j-half (w>>2)*32.
// A frags (16 rows x k64) resident in 16 regs/thread. j streamed 64 cols/tile, 32 tiles.
// Rank by s = x2j(fp32) - 2*dot(bf16); density = tanh(mean 5 NN dists) is tanh-saturated,
// so bf16 gram noise (~0.04 on d2 vs NN d2 ~90) is far below output precision.
__device__ __forceinline__ void ins6(float t[6], float v){
    if (v < t[5]){
        t[5]=v;
        #pragma unroll
        for (int s=5;s>0;s--){ if (t[s]<t[s-1]){ float tmp=t[s-1]; t[s-1]=t[s]; t[s]=tmp; } }
    }
}

#define JT_STRIDE 72   // bf16 elems per staged row (64 + 8 pad) -> conflict-free b-frag LDS

__global__ void __launch_bounds__(256) dens_kernel(float* __restrict__ dens_out)
{
    __shared__ float smf[3200];                       // 12800 B union
    __nv_bfloat16* sxj = (__nv_bfloat16*)smf;         // [64][72] bf16 = 9216 B
    float* x2s  = smf + (64*JT_STRIDE*2)/4;           // 64 floats at 9216 B
    float* cand = smf;                                // reuse after loop: [64][49]

    const int b  = blockIdx.y;
    const int i0 = blockIdx.x * 64;
    const int tid = threadIdx.x, w = tid>>5, lane = tid&31;
    const int g = lane>>2, tg = lane&3;
    const int rg = w & 3;           // row group (16 rows)
    const int jh = w >> 2;          // j half (32 cols)
    const int r0 = i0 + rg*16 + g;  // rows r0 (c0,c1) and r0+8 (c2,c3)
    const unsigned short* xb = (const unsigned short*)g_xbf2 + (size_t)b*NNP*IND;

    // resident A fragments: 4 ksteps x 4 regs
    unsigned int A[4][4];
    {
        const unsigned short* xr0 = xb + (size_t)r0*IND;
        const unsigned short* xr1 = xr0 + 8*IND;
        #pragma unroll
        for (int ks=0;ks<4;ks++){
            int kb = ks*16 + tg*2;
            A[ks][0] = *(const unsigned int*)&xr0[kb];
            A[ks][1] = *(const unsigned int*)&xr1[kb];
            A[ks][2] = *(const unsigned int*)&xr0[kb+8];
            A[ks][3] = *(const unsigned int*)&xr1[kb+8];
        }
    }
    float t6[2][6];
    #pragma unroll
    for (int r=0;r<2;r++){
        #pragma unroll
        for (int s=0;s<6;s++) t6[r][s]=1e30f;
    }

    for (int jt=0; jt<32; jt++){
        __syncthreads();
        {   // stage 64 j-rows x 64 bf16 (each warp copies one full 128B row per step)
            #pragma unroll
            for (int p=0;p<8;p++){
                int idx = tid + 256*p;                 // 2048 u32
                int row = idx >> 5, c = idx & 31;
                unsigned int v = *(const unsigned int*)&xb[((size_t)(jt*64 + row))*IND + c*2];
                *(unsigned int*)&sxj[row*JT_STRIDE + c*2] = v;
            }
            if (tid < 64) x2s[tid] = g_x2[b*NNP + jt*64 + tid];
        }
        __syncthreads();
        #pragma unroll
        for (int q=0;q<4;q++){
            const int nt = jh*4 + q;
            const int n  = nt*8 + g;
            float c0=0.f,c1=0.f,c2=0.f,c3=0.f;
            #pragma unroll
            for (int ks=0;ks<4;ks++){
                const __nv_bfloat16* bp = &sxj[n*JT_STRIDE + ks*16 + tg*2];
                unsigned int B0 = *(const unsigned int*)bp;
                unsigned int B1 = *(const unsigned int*)(bp+8);
                asm("mma.sync.aligned.m16n8k16.row.col.f32.bf16.bf16.f32 "
                    "{%0,%1,%2,%3}, {%4,%5,%6,%7}, {%8,%9}, {%0,%1,%2,%3};"
                    : "+f"(c0),"+f"(c1),"+f"(c2),"+f"(c3)
                    : "r"(A[ks][0]),"r"(A[ks][1]),"r"(A[ks][2]),"r"(A[ks][3]),
                      "r"(B0),"r"(B1));
            }
            const int lc = nt*8 + tg*2;
            float xa = x2s[lc], xc = x2s[lc+1];
            ins6(t6[0], xa - 2.f*c0); ins6(t6[0], xc - 2.f*c1);
            ins6(t6[1], xa - 2.f*c2); ins6(t6[1], xc - 2.f*c3);
        }
    }
    __syncthreads();
    {
        int lr0 = rg*16 + g;
        int base = jh*24 + tg*6;
        #pragma unroll
        for (int s=0;s<6;s++){
            cand[lr0*49 + base + s]     = t6[0][s];
            cand[(lr0+8)*49 + base + s] = t6[1][s];
        }
    }
    __syncthreads();
    if (tid < 64){
        float u[6]={1e30f,1e30f,1e30f,1e30f,1e30f,1e30f};
        const float* row = &cand[tid*49];
        #pragma unroll 8
        for (int m=0;m<48;m++) ins6(u, row[m]);
        float x2i = g_x2[b*NNP + i0 + tid];
        float md = (sqrtf(fmaxf(x2i+u[1],0.f)) + sqrtf(fmaxf(x2i+u[2],0.f))
                  + sqrtf(fmaxf(x2i+u[3],0.f)) + sqrtf(fmaxf(x2i+u[4],0.f))
                  + sqrtf(fmaxf(x2i+u[5],0.f))) * 0.2f;
        float dv = tanhf(md);
        g_density[b*NNP + i0 + tid] = dv;
        dens_out [b*NNP + i0 + tid] = dv;
    }
}

// ======================= feats: Poincare projection =======================
__global__ void feats_kernel()
{
    const int w = threadIdx.x>>5, l = threadIdx.x&31;
    const int n = blockIdx.x*8 + w;
    float4 v = ((const float4*)(g_hyp + (size_t)n*HD))[l];
    float q = v.x*v.x+v.y*v.y+v.z*v.z+v.w*v.w;
    #pragma unroll
    for (int o=16;o;o>>=1) q += __shfl_xor_sync(0xffffffffu,q,o);
    float fn = fmaxf(sqrtf(q),1e-6f);
    float dens = g_density[n];
    float tr = (0.3f+0.5f*(1.f-dens))*0.95f;
    float sc = tr/fn;
    float4 f = make_float4(v.x*sc,v.y*sc,v.z*sc,v.w*sc);
    ((float4*)(g_feats + (size_t)n*HD))[l]=f;
    if (l==0){
        float f2=q*sc*sc;
        g_f2[n]=f2; g_fr[n]=sqrtf(f2);
    }
}

// ======================= slots init =======================
__global__ void slots_init_kernel(const float* __restrict__ obj_dirs)
{
    const int w=threadIdx.x>>5, l=threadIdx.x&31;
    if (w<NOBJ){
        float4 v=((const float4*)(obj_dirs + w*HD))[l];
        float q=v.x*v.x+v.y*v.y+v.z*v.z+v.w*v.w;
        #pragma unroll
        for (int o=16;o;o>>=1) q += __shfl_xor_sync(0xffffffffu,q,o);
        float nrm=sqrtf(q);
        float inv=1.f/fmaxf(nrm,1e-12f);
        float4 dn=make_float4(v.x*inv,v.y*inv,v.z*inv,v.w*inv);
        float qn=q*inv*inv;
        const float radii[3]={0.2f,0.5f,0.8f};
        for (int b=0;b<BB;b++){
            #pragma unroll
            for (int lv=0;lv<3;lv++){
                float r=radii[lv];
                ((float4*)(g_slots + (size_t)(b*NSLOT + w*3+lv)*HD))[l] =
                    make_float4(dn.x*r,dn.y*r,dn.z*r,dn.w*r);
                if (l==0){
                    float s2=qn*r*r;
                    g_s2[b*NSLOT + w*3+lv]=s2;
                    g_sr[b*NSLOT + w*3+lv]=sqrtf(s2);
                }
            }
        }
    }
}

// ======================= gh precompute =======================
__global__ void gh_kernel(const float* __restrict__ obj_dirs,
                          const float* __restrict__ gru_wh,
                          const float* __restrict__ gru_bh)
{
    const int o = blockIdx.x;
    const int w = threadIdx.x>>5, l = threadIdx.x&31;
    float4 od = ((const float4*)(obj_dirs + (size_t)o*HD))[l];
    for (int m=0;m<48;m++){
        int r = w*48 + m;
        float4 wv = ((const float4*)(gru_wh + (size_t)r*HD))[l];
        float p = od.x*wv.x + od.y*wv.y + od.z*wv.z + od.w*wv.w;
        #pragma unroll
        for (int of=16;of;of>>=1) p += __shfl_xor_sync(0xffffffffu,p,of);
        if (l==0) g_gh[o*3*HD + r] = p + gru_bh[r];
    }
}

// ======================= zero scratch (once) =======================
__global__ void zero_kernel()
{
    int i = blockIdx.x*256 + threadIdx.x;
    if (i < BB*NSLOT*HD) g_upd[i]=0.f;
    if (i < BB*NSLOT)    g_rowsum[i]=0.f;
}

// ======================= attention iteration =======================
__global__ void __launch_bounds__(256) attn_kernel(const float* __restrict__ rs_ptr,
                                                   float* __restrict__ attn_out)
{
    __shared__ float s_slots[NSLOT*HD];
    __shared__ float s_s2[NSLOT], s_sr[NSLOT];
    const int b = blockIdx.x >> 4;
    const int nbase = (blockIdx.x & 15) * 128;
    const int tid=threadIdx.x, w=tid>>5, l=tid&31;
    {
        const float4* ss=(const float4*)(g_slots + (size_t)b*NSLOT*HD);
        float4* sd=(float4*)s_slots;
        for (int i=tid;i<NSLOT*HD/4;i+=256) sd[i]=ss[i];
        if (tid<NSLOT){ s_s2[tid]=g_s2[b*NSLOT+tid]; s_sr[tid]=g_sr[b*NSLOT+tid]; }
    }
    __syncthreads();
    const float rs = *rs_ptr;
    float4 acc[NSLOT];
    #pragma unroll
    for (int k=0;k<NSLOT;k++) acc[k]=make_float4(0.f,0.f,0.f,0.f);
    float rsum=0.f;
    const int lvl = (l<NSLOT)? (l - (l/3)*3) : 0;
    const float basel = (lvl==0)?2.f:((lvl==1)?1.f:0.5f);
    const float s2k = (l<NSLOT)? s_s2[l] : 0.f;
    const float srk = (l<NSLOT)? s_sr[l] : 0.f;
    const float4* slots4=(const float4*)s_slots;

    for (int ii=0;ii<16;ii++){
        const int n = nbase + w*16 + ii;
        const size_t off = (size_t)b*NNP + n;
        float4 f = ((const float4*)(g_feats + off*HD))[l];
        float f2n = g_f2[off];
        float frn = g_fr[off];
        float dens= g_density[off];
        float mod = rs*(dens-0.5f);
        float mydot=0.f;
        #pragma unroll
        for (int k=0;k<NSLOT;k++){
            float4 sv=slots4[k*32+l];
            float p = f.x*sv.x+f.y*sv.y+f.z*sv.z+f.w*sv.w;
            p += __shfl_xor_sync(0xffffffffu,p,16);
            p += __shfl_xor_sync(0xffffffffu,p,8);
            p += __shfl_xor_sync(0xffffffffu,p,4);
            p += __shfl_xor_sync(0xffffffffu,p,2);
            p += __shfl_xor_sync(0xffffffffu,p,1);
            if (l==k) mydot=p;
        }
        float logit=-1e30f;
        if (l<NSLOT){
            float diff2 = fmaxf(f2n + s2k - 2.f*mydot, 0.f);
            float xn = fminf(f2n, 1.f-1e-5f);
            float yn = fminf(s2k, 1.f-1e-5f);
            float den = fmaxf((1.f-xn)*(1.f-yn), 1e-6f);
            float arg = fmaxf(1.f + 2.f*diff2/den, 1.f+1e-6f);
            float hd = acoshf(arg);
            float rd = fabsf(frn-srk);
            float scv = fminf(fmaxf(basel+mod,0.3f),3.f);
            logit = (-hd - 3.f*rd)*scv*10.f;   // /TAU
        }
        float m=logit;
        #pragma unroll
        for (int o=16;o;o>>=1) m=fmaxf(m,__shfl_xor_sync(0xffffffffu,m,o));
        float e=(l<NSLOT)? expf(logit-m):0.f;
        float s=e;
        #pragma unroll
        for (int o=16;o;o>>=1) s+=__shfl_xor_sync(0xffffffffu,s,o);
        float a=e/s;
        if (l<NSLOT){
            attn_out[((size_t)b*NSLOT+l)*NNP + n]=a;
            rsum += a;
        }
        #pragma unroll
        for (int k=0;k<NSLOT;k++){
            float ak=__shfl_sync(0xffffffffu,a,k);
            acc[k].x=fmaf(ak,f.x,acc[k].x); acc[k].y=fmaf(ak,f.y,acc[k].y);
            acc[k].z=fmaf(ak,f.z,acc[k].z); acc[k].w=fmaf(ak,f.w,acc[k].w);
        }
    }
    if (l<NSLOT) atomicAdd(&g_rowsum[b*NSLOT+l], rsum);
    #pragma unroll
    for (int k=0;k<NSLOT;k++){
        float* up = g_upd + ((size_t)b*NSLOT+k)*HD + l*4;
        atomicAdd(up+0,acc[k].x); atomicAdd(up+1,acc[k].y);
        atomicAdd(up+2,acc[k].z); atomicAdd(up+3,acc[k].w);
    }
}

// ======================= GRU + MLP + renorm (+ zero consumed scratch) =======================
__device__ __forceinline__ float blksum128(float v, volatile float* red){
    #pragma unroll
    for (int o=16;o;o>>=1) v += __shfl_xor_sync(0xffffffffu,v,o);
    __syncthreads();
    if ((threadIdx.x&31)==0) red[threadIdx.x>>5]=v;
    __syncthreads();
    return red[0]+red[1]+red[2]+red[3];
}

__global__ void gru_kernel(const float* __restrict__ obj_dirs,
    const float* __restrict__ gru_wi, const float* __restrict__ gru_bi,
    const float* __restrict__ mlp_w1, const float* __restrict__ mlp_b1,
    const float* __restrict__ mlp_w2, const float* __restrict__ mlp_b2,
    const float* __restrict__ norm_g, const float* __restrict__ norm_b,
    float* __restrict__ slots_out)
{
    __shared__ float s_buf[HD];
    __shared__ float s_red[4];
    const int b = blockIdx.x >> 3, o = blockIdx.x & 7;
    const int h = threadIdx.x;
    float ou=0.f;
    #pragma unroll
    for (int lv=0;lv<3;lv++){
        int k=o*3+lv;
        ou += g_upd[((size_t)b*NSLOT+k)*HD + h] / (g_rowsum[b*NSLOT+k]+1e-8f);
    }
    s_buf[h]=ou; __syncthreads();
    #pragma unroll
    for (int lv=0;lv<3;lv++){
        int k=o*3+lv;
        g_upd[((size_t)b*NSLOT+k)*HD + h]=0.f;
        if (h==lv) g_rowsum[b*NSLOT+k]=0.f;
    }
    float gi[3];
    #pragma unroll
    for (int p=0;p<3;p++){
        int r=p*HD+h;
        float a=gru_bi[r];
        const float* wr=gru_wi+(size_t)r*HD;
        #pragma unroll 8
        for (int hh=0;hh<HD;hh++) a=fmaf(s_buf[hh],wr[hh],a);
        gi[p]=a;
    }
    float hr=g_gh[o*3*HD + h], hz=g_gh[o*3*HD + HD + h], hn=g_gh[o*3*HD + 2*HD + h];
    float rr=sigmoidf(gi[0]+hr);
    float z =sigmoidf(gi[1]+hz);
    float nnv=tanhf(gi[2]+rr*hn);
    float oldh=obj_dirs[o*HD+h];
    float nd=(1.f-z)*nnv + z*oldh;
    float s = blksum128(nd, s_red);
    float q = blksum128(nd*nd, s_red);
    float mu=s*(1.f/HD), var=q*(1.f/HD)-mu*mu;
    float ln=(nd-mu)*rsqrtf(var+1e-5f)*norm_g[h]+norm_b[h];
    __syncthreads(); s_buf[h]=ln; __syncthreads();
    float m1=mlp_b1[h];
    {
        const float* w1=mlp_w1;
        #pragma unroll 8
        for (int hh=0;hh<HD;hh++) m1=fmaf(s_buf[hh],w1[(size_t)hh*HD+h],m1);
    }
    m1=geluf(m1);
    __syncthreads(); s_buf[h]=m1; __syncthreads();
    float m2=mlp_b2[h];
    {
        const float* w2=mlp_w2;
        #pragma unroll 8
        for (int hh=0;hh<HD;hh++) m2=fmaf(s_buf[hh],w2[(size_t)hh*HD+h],m2);
    }
    float nd2 = nd + 0.2f*m2;
    float q2 = blksum128(nd2*nd2, s_red);
    float nrm = fmaxf(sqrtf(q2),1e-12f);
    float ndn = nd2/nrm;
    float qn = q2/(nrm*nrm);
    const float radii[3]={0.2f,0.5f,0.8f};
    #pragma unroll
    for (int lv=0;lv<3;lv++){
        float r=radii[lv];
        float v=ndn*r;
        size_t idx=((size_t)b*NSLOT + o*3+lv)*HD + h;
        g_slots[idx]=v;
        slots_out[idx]=v;
    }
    if (h<3){
        float r=radii[h];
        float s2v=qn*r*r;
        g_s2[b*NSLOT + o*3 + h]=s2v;
        g_sr[b*NSLOT + o*3 + h]=sqrtf(s2v);
    }
}

// ======================= host launch =======================
extern "C" void kernel_launch(void* const* d_in, const int* in_sizes, int n_in,
                              void* d_out, int out_size)
{
    const float* x      = (const float*)d_in[0];
    const float* fe_w1  = (const float*)d_in[1];
    const float* fe_b1  = (const float*)d_in[2];
    const float* ln1_g  = (const float*)d_in[3];
    const float* ln1_b  = (const float*)d_in[4];
    const float* fe_w2  = (const float*)d_in[5];
    const float* fe_b2  = (const float*)d_in[6];
    const float* ln2_g  = (const float*)d_in[7];
    const float* ln2_b  = (const float*)d_in[8];
    const float* hp_w   = (const float*)d_in[9];
    const float* hp_b   = (const float*)d_in[10];
    const float* obj_dirs = (const float*)d_in[11];
    const float* radius_scale = (const float*)d_in[12];
    const float* gru_wi = (const float*)d_in[13];
    const float* gru_wh = (const float*)d_in[14];
    const float* gru_bi = (const float*)d_in[15];
    const float* gru_bh = (const float*)d_in[16];
    const float* mlp_w1 = (const float*)d_in[17];
    const float* mlp_b1 = (const float*)d_in[18];
    const float* mlp_w2 = (const float*)d_in[19];
    const float* mlp_b2 = (const float*)d_in[20];
    const float* norm_g = (const float*)d_in[21];
    const float* norm_b = (const float*)d_in[22];

    float* out = (float*)d_out;
    float* slots_out = out;                                   // [16,24,128]
    float* attn_out  = out + BB*NSLOT*HD;                     // [16,24,2048]
    float* dens_out  = attn_out + (size_t)BB*NSLOT*NNP;       // [16,2048]

    size_t encSmem = (size_t)(HD*HD + 32*IND + 32*HD)*sizeof(float);   // 90KB
    cudaFuncSetAttribute(enc_kernel, cudaFuncAttributeMaxDynamicSharedMemorySize, (int)encSmem);

    // Order keeps dens_kernel at 0-based launch index 3 (the ncu capture point).
    enc_kernel<<<BB*NNP/32, 128, encSmem>>>(x, fe_w1, fe_b1, ln1_g, ln1_b,
                                            fe_w2, fe_b2, ln2_g, ln2_b, hp_w, hp_b);   // 0
    xbf_kernel<<<BB*NNP*IND/2/256, 256>>>(x);                                          // 1
    gh_kernel<<<NOBJ, 256>>>(obj_dirs, gru_wh, gru_bh);                                // 2
    {
        dim3 g(NNP/64, BB);
        dens_kernel<<<g, 256>>>(dens_out);                                             // 3 <- profiled
    }
    slots_init_kernel<<<1, 256>>>(obj_dirs);                                           // 4
    feats_kernel<<<BB*NNP/8, 256>>>();                                                 // 5
    zero_kernel<<<(BB*NSLOT*HD+255)/256, 256>>>();                                     // 6

    for (int it=0; it<NITER; it++){
        attn_kernel<<<BB*16, 256>>>(radius_scale, attn_out);
        gru_kernel<<<BB*NOBJ, 128>>>(obj_dirs, gru_wi, gru_bi,
                                     mlp_w1, mlp_b1, mlp_w2, mlp_b2,
                                     norm_g, norm_b, slots_out);
    }
}